// round 9
// baseline (speedup 1.0000x reference)
#include <cuda_runtime.h>
#include <cuda_bf16.h>
#include <math.h>

// Router: N=8192 tokens, C=1024, E=8 experts, top-2, cap=2560.
// Output (float32): [used_capacity(8) | cb_weight(N*E*cap) | sec_mask(N*E*cap)]

#define C_EMB 1024
#define N_EXP 8
#define TOPK  2
#define MAXN  8192
#define GEMM_BLKS 256
#define RANK_BLKS 64                      // (TOPK*MAXN)/256
#define GRID_BLKS (148 * 8)               // 1184
#define TILE_F4  2048                     // 32KB fill tile per warp-ticket

// Scratch (priority order i = k*N + n)
__device__ int   g_idx  [TOPK * MAXN];
__device__ float g_prob [TOPK * MAXN];
__device__ int   g_lrank[TOPK * MAXN];
__device__ int   g_bhist[RANK_BLKS * N_EXP];
// [0]=gemm_done [1]=rank_done [2]=fill_done [3]=fill ticket — memset to 0 each launch
__device__ int   g_ctr[4];

// ---------------------------------------------------------------------------
// Single fused kernel: gemm -> (blocks 0..63) rank -> everyone fills via
// ticket -> (blocks 0..63) wait for fill completion, prefix + scatter.
// ---------------------------------------------------------------------------
__global__ __launch_bounds__(256) void fused_all(
    float4* __restrict__ out4, long n4,
    const float* __restrict__ x, const float* __restrict__ wg,
    int N, int cap, float* __restrict__ out)
{
    const int tid  = threadIdx.x;
    const int lane = tid & 31;
    const int w    = tid >> 5;
    const int bid  = blockIdx.x;
    const int rblocks = (TOPK * N) / 256;      // 64

    __shared__ int s_whist[8][N_EXP];
    __shared__ int s_boff[N_EXP];
    __shared__ int s_tot [N_EXP];

    // ---------------- Phase A: gemm (blocks 0..255) ----------------
    if (bid < GEMM_BLKS) {
        const int warp_g = bid * 8 + w;        // 2048 warps, 4 tokens each
        for (int t = 0; t < 4; t++) {
            const int n = warp_g + t * (GEMM_BLKS * 8);
            if (n >= N) break;
            const float4* xr = reinterpret_cast<const float4*>(x + (size_t)n * C_EMB);
            float acc[N_EXP];
#pragma unroll
            for (int e = 0; e < N_EXP; e++) acc[e] = 0.f;
#pragma unroll
            for (int it = 0; it < C_EMB / (32 * 4); it++) {
                float4 v = xr[lane + it * 32];
#pragma unroll
                for (int e = 0; e < N_EXP; e++) {
                    float4 ww = __ldg(reinterpret_cast<const float4*>(wg + e * C_EMB) + lane + it * 32);
                    acc[e] += v.x * ww.x + v.y * ww.y + v.z * ww.z + v.w * ww.w;
                }
            }
#pragma unroll
            for (int off = 16; off; off >>= 1)
#pragma unroll
                for (int e = 0; e < N_EXP; e++)
                    acc[e] += __shfl_xor_sync(0xffffffffu, acc[e], off);

            if (lane == 0) {
                int e0 = 0; float l0 = acc[0];
#pragma unroll
                for (int e = 1; e < N_EXP; e++) if (acc[e] > l0) { l0 = acc[e]; e0 = e; }
                int e1 = -1; float l1 = -INFINITY;
#pragma unroll
                for (int e = 0; e < N_EXP; e++) if (e != e0 && acc[e] > l1) { l1 = acc[e]; e1 = e; }
                float tt  = __expf(l1 - l0);    // <= 1
                float inv = 1.f / (1.f + tt);
                g_idx [n]     = e0;  g_prob[n]     = inv;
                g_idx [N + n] = e1;  g_prob[N + n] = tt * inv;
            }
        }
        __syncthreads();
        if (tid == 0) { __threadfence(); atomicAdd(&g_ctr[0], 1); }
    }

    // ---------------- Phase B: local rank (blocks 0..63) ----------------
    // Blocks 0..255 are all wave-1 resident, so spinning here is deadlock-free.
    if (bid < rblocks) {
        if (tid == 0)
            while (atomicAdd(&g_ctr[0], 0) < GEMM_BLKS) __nanosleep(64);
        __syncthreads();
        __threadfence();                       // acquire published g_idx

        const int i = bid * 256 + tid;
        int e = g_idx[i];
        unsigned m = __match_any_sync(0xffffffffu, e);
        int lrank = __popc(m & ((1u << lane) - 1u));

        if (tid < 8 * N_EXP) ((int*)s_whist)[tid] = 0;
        __syncthreads();
        if (lane == (__ffs(m) - 1)) s_whist[w][e] = __popc(m);
        __syncthreads();

        int woff = 0;
#pragma unroll
        for (int w2 = 0; w2 < 8; w2++)
            if (w2 < w) woff += s_whist[w2][e];
        g_lrank[i] = lrank + woff;

        if (tid < N_EXP) {
            int tot = 0;
#pragma unroll
            for (int w2 = 0; w2 < 8; w2++) tot += s_whist[w2][tid];
            g_bhist[bid * N_EXP + tid] = tot;
        }
        __syncthreads();
        if (tid == 0) { __threadfence(); atomicAdd(&g_ctr[1], 1); }
    }

    // ---------------- Fill phase: ticketed 32KB tiles, all blocks ----------------
    {
        const float4 z = make_float4(0.f, 0.f, 0.f, 0.f);
        unsigned* ticket = (unsigned*)&g_ctr[3];
        for (;;) {
            unsigned t;
            if (lane == 0) t = atomicAdd(ticket, 1u);
            t = __shfl_sync(0xffffffffu, t, 0);
            long base = (long)t * TILE_F4;
            if (base >= n4) break;
            long end = base + TILE_F4 < n4 ? base + TILE_F4 : n4;
#pragma unroll 4
            for (long i = base + lane; i < end; i += 32)
                __stcs(&out4[i], z);
        }
    }
    __syncthreads();
    if (tid == 0) { __threadfence(); atomicAdd(&g_ctr[2], 1); }

    // ---------------- Final phase: prefix + scatter (blocks 0..63) ----------------
    // Must run after ALL fill stores (scatter writes land on zeroed lines).
    // Non-scatter blocks simply retire, so spinners cannot starve them.
    if (bid < rblocks) {
        if (tid == 0) {
            while (atomicAdd(&g_ctr[2], 0) < (int)gridDim.x) __nanosleep(128);
            while (atomicAdd(&g_ctr[1], 0) < rblocks)        __nanosleep(64);
        }
        __syncthreads();
        __threadfence();

        // warp-per-expert shuffle scan over block histograms (rblocks <= 64)
        {
            int b0 = 2 * lane, b1 = 2 * lane + 1;
            int c0 = (b0 < rblocks) ? g_bhist[b0 * N_EXP + w] : 0;
            int c1 = (b1 < rblocks) ? g_bhist[b1 * N_EXP + w] : 0;
            int pair = c0 + c1;
            int scan = pair;
#pragma unroll
            for (int off = 1; off < 32; off <<= 1) {
                int v = __shfl_up_sync(0xffffffffu, scan, off);
                if (lane >= off) scan += v;
            }
            int excl = scan - pair;
            int srcl = bid >> 1;
            int exclv = __shfl_sync(0xffffffffu, excl, srcl);
            int c0v   = __shfl_sync(0xffffffffu, c0,   srcl);
            int off_b = exclv + ((bid & 1) ? c0v : 0);
            int total = __shfl_sync(0xffffffffu, scan, 31);
            if (lane == 0) { s_boff[w] = off_b; s_tot[w] = total; }
        }
        __syncthreads();

        if (bid == 0 && tid < N_EXP) {
            int u = s_tot[tid];
            out[tid] = (float)(u < cap ? u : cap);   // used_capacity
        }

        const int i = bid * 256 + tid;
        int e = g_idx[i];
        int r = g_lrank[i] + s_boff[e];
        if (r < cap) {
            int n = i & (N - 1);                     // i = k*N + n, N power of 2
            float p = g_prob[i];
            size_t o = (size_t)N_EXP + (size_t)n * (N_EXP * cap) + (size_t)e * cap + r;
            out[o] = p;
            out[o + (size_t)N * N_EXP * cap] = (p != 0.f) ? 1.f : 0.f;
        }
    }
}

// ---------------------------------------------------------------------------
extern "C" void kernel_launch(void* const* d_in, const int* in_sizes, int n_in,
                              void* d_out, int out_size)
{
    const float* x  = (const float*)d_in[0];
    const float* wg = (const float*)d_in[1];
    int N = in_sizes[0] / C_EMB;      // 8192

    int cap = (5 * N) / 16;           // floor(2 * 1.25 * N / 8)
    cap += (cap & 1);
    if (cap < 4) cap = 4;

    // Reset all intra-kernel counters (gemm/rank/fill/ticket) — 16 bytes
    void* ctr_addr = nullptr;
    cudaGetSymbolAddress(&ctr_addr, g_ctr);
    cudaMemsetAsync(ctr_addr, 0, 4 * sizeof(int), 0);

    long n4 = (long)out_size / 4;     // out_size divisible by 4
    fused_all<<<GRID_BLKS, 256>>>((float4*)d_out, n4, x, wg, N, cap, (float*)d_out);
}